// round 15
// baseline (speedup 1.0000x reference)
#include <cuda_runtime.h>
#include <cuda_fp16.h>
#include <math.h>
#include <stdint.h>

// ---------------------------------------------------------------------------
// Problem constants
// ---------------------------------------------------------------------------
#define DIMD 2048
#define HID  3840
#define NTOK 8192
#define NEXP 4
#define EPSV 1e-5f
#define BM 128
#define BN1 64           // GEMM1 N-tile (gate+up dual output)
#define BN2 128          // GEMM2 N-tile
#define MAX_TILES (NTOK / BM + NEXP)

#define G1_NK (DIMD / 64)   // 32 K-chunks of 64
#define G2_NK (HID / 64)    // 60 K-chunks of 64
#define NSTAGE 3

// Stage layouts (bytes)
#define G1_STAGE 32768      // A 16KB + B1 8KB + B3 8KB
#define G1_B1OFF 16384
#define G1_B3OFF 24576
#define G2_STAGE 32768      // A 16KB + B 16KB
#define G2_BOFF  16384

// SW128 swizzle (Swizzle<3,4,3>) on byte offsets within a tile
#define SW(o) ((o) ^ (((o) >> 3) & 0x70))

// ---------------------------------------------------------------------------
// Scratch (device globals: allocation-free)
// ---------------------------------------------------------------------------
__device__ __half g_x[(size_t)NTOK * DIMD];
__device__ __half g_w1[(size_t)NEXP * HID * DIMD];
__device__ __half g_w3[(size_t)NEXP * HID * DIMD];
__device__ __half g_w2[(size_t)NEXP * DIMD * HID];
__device__ __half g_h[(size_t)NTOK * HID];
__device__ __half g_y[(size_t)NTOK * DIMD];
__device__ int   g_perm[NTOK];
__device__ int   g_tile_e[MAX_TILES];
__device__ int   g_tile_row0[MAX_TILES];
__device__ int   g_tile_rows[MAX_TILES];
__device__ int   g_ntiles;

// ---------------------------------------------------------------------------
// PTX helpers (sm_80-baseline)
// ---------------------------------------------------------------------------
__device__ __forceinline__ uint32_t smem_u32(const void* p) {
    uint32_t a;
    asm("{ .reg .u64 t; cvta.to.shared.u64 t, %1; cvt.u32.u64 %0, t; }" : "=r"(a) : "l"(p));
    return a;
}
__device__ __forceinline__ void cpasync16(uint32_t dst, const void* src) {
    asm volatile("cp.async.cg.shared.global [%0], [%1], 16;" :: "r"(dst), "l"(src) : "memory");
}
__device__ __forceinline__ void cp_commit() {
    asm volatile("cp.async.commit_group;" ::: "memory");
}
__device__ __forceinline__ void cp_wait1() {
    asm volatile("cp.async.wait_group 1;" ::: "memory");
}
__device__ __forceinline__ void cp_wait0() {
    asm volatile("cp.async.wait_group 0;" ::: "memory");
}
__device__ __forceinline__ void ldsm4(uint32_t* r, uint32_t addr) {
    asm volatile("ldmatrix.sync.aligned.m8n8.x4.shared.b16 {%0,%1,%2,%3}, [%4];"
                 : "=r"(r[0]), "=r"(r[1]), "=r"(r[2]), "=r"(r[3]) : "r"(addr));
}
__device__ __forceinline__ void mma16816(float* d, const uint32_t* a, const uint32_t* b) {
    asm volatile("mma.sync.aligned.m16n8k16.row.col.f32.f16.f16.f32 "
                 "{%0,%1,%2,%3}, {%4,%5,%6,%7}, {%8,%9}, {%0,%1,%2,%3};"
                 : "+f"(d[0]), "+f"(d[1]), "+f"(d[2]), "+f"(d[3])
                 : "r"(a[0]), "r"(a[1]), "r"(a[2]), "r"(a[3]), "r"(b[0]), "r"(b[1]));
}
__device__ __forceinline__ uint2 cvt4_f32_f16(float4 f) {
    __half h0 = __float2half_rn(f.x);
    __half h1 = __float2half_rn(f.y);
    __half h2 = __float2half_rn(f.z);
    __half h3 = __float2half_rn(f.w);
    uint2 H;
    H.x = (uint32_t)__half_as_ushort(h0) | ((uint32_t)__half_as_ushort(h1) << 16);
    H.y = (uint32_t)__half_as_ushort(h2) | ((uint32_t)__half_as_ushort(h3) << 16);
    return H;
}

// ---------------------------------------------------------------------------
// Routing
// ---------------------------------------------------------------------------
__global__ void route_kernel(const int* __restrict__ ids) {
    __shared__ int cnt[NEXP];
    __shared__ int cur[NEXP];
    int tid = threadIdx.x;
    if (tid < NEXP) cnt[tid] = 0;
    __syncthreads();
    for (int t = tid; t < NTOK; t += blockDim.x) atomicAdd(&cnt[ids[t]], 1);
    __syncthreads();
    if (tid == 0) {
        int o = 0, nt = 0;
        for (int e = 0; e < NEXP; e++) {
            cur[e] = o;
            int c = cnt[e];
            for (int r = 0; r < c; r += BM) {
                g_tile_e[nt] = e;
                g_tile_row0[nt] = o + r;
                g_tile_rows[nt] = (c - r) < BM ? (c - r) : BM;
                nt++;
            }
            o += c;
        }
        g_ntiles = nt;
    }
    __syncthreads();
    for (int t = tid; t < NTOK; t += blockDim.x) {
        int p = atomicAdd(&cur[ids[t]], 1);
        g_perm[p] = t;
    }
}

// ---------------------------------------------------------------------------
// fp32 -> fp16 (rn) for w1, w3, x. (w2 is converted inside gemm1's extra
// grid slice, overlapping with gemm1's tensor-bound compute.)
// ---------------------------------------------------------------------------
#define WN4 ((NEXP * HID * DIMD) / 4)
#define XN4 ((NTOK * DIMD) / 4)
#define TOT3N4 (2 * WN4 + XN4)

__global__ __launch_bounds__(256) void cvt3_kernel(
    const float* __restrict__ w1, const float* __restrict__ w3,
    const float* __restrict__ x)
{
    int stride = gridDim.x * blockDim.x;
    for (int i = blockIdx.x * blockDim.x + threadIdx.x; i < TOT3N4; i += stride) {
        const float4* src;
        uint2* dst;
        int j = i;
        if (j < WN4)               { src = (const float4*)w1; dst = (uint2*)g_w1; }
        else if ((j -= WN4) < WN4) { src = (const float4*)w3; dst = (uint2*)g_w3; }
        else { j -= WN4;             src = (const float4*)x;  dst = (uint2*)g_x; }
        dst[j] = cvt4_f32_f16(src[j]);
    }
}

// ---------------------------------------------------------------------------
// GEMM1: gate=X*W1^T, up=X*W3^T, h=silu(gate)*up.
// CTA tile 128x64, warp tile 32x32 (4Mx2N warps). 2 CTAs/SM.
// Stage = [A 16KB | B1 8KB | B3 8KB]; 3-stage cp.async pipeline (96KB).
// Extra grid slice (blockIdx.y == HID/BN1) converts w2 fp32->fp16 in overlap
// with the GEMM CTAs (DRAM path is idle under the tensor-bound mainloop).
// ---------------------------------------------------------------------------
__global__ __launch_bounds__(256, 2) void gemm1_tc(const float* __restrict__ w2src) {
    const int tid  = threadIdx.x;

    if (blockIdx.y == HID / BN1) {
        // w2 conversion slice: grid-stride over WN4 float4s.
        const float4* src = (const float4*)w2src;
        uint2* dst = (uint2*)g_w2;
        int stride = MAX_TILES * 256;
        for (int i = blockIdx.x * 256 + tid; i < WN4; i += stride)
            dst[i] = cvt4_f32_f16(src[i]);
        return;
    }

    const int tileId = blockIdx.x;
    if (tileId >= g_ntiles) return;
    const int e    = g_tile_e[tileId];
    const int row0 = g_tile_row0[tileId];
    const int rows = g_tile_rows[tileId];
    const int bn0  = blockIdx.y * BN1;
    const int wid  = tid >> 5, lid = tid & 31;
    const int warp_m = (wid >> 1) * 32;   // 0,32,64,96
    const int warp_n = (wid & 1) * 32;    // 0,32

    extern __shared__ char dynsm[];
    uint32_t sb_raw = smem_u32(dynsm);
    uint32_t sb = (sb_raw + 1023u) & ~1023u;

    __shared__ int rowTok[BM];
    if (tid < BM) rowTok[tid] = g_perm[row0 + (tid < rows ? tid : rows - 1)];
    __syncthreads();

    const __half* w1p = g_w1 + ((size_t)e * HID + bn0) * DIMD;
    const __half* w3p = g_w3 + ((size_t)e * HID + bn0) * DIMD;

    auto load_chunk = [&](int st, int k0) {
        uint32_t base = sb + st * G1_STAGE;
#pragma unroll
        for (int i = 0; i < 4; i++) {               // A: 128x64
            int seg = tid + i * 256;
            int r = seg >> 3, s = seg & 7;
            uint32_t so = SW(r * 128 + s * 16);
            cpasync16(base + so, g_x + (size_t)rowTok[r] * DIMD + k0 + s * 8);
        }
#pragma unroll
        for (int i = 0; i < 2; i++) {               // B1, B3: 64x64 each
            int seg = tid + i * 256;
            int r = seg >> 3, s = seg & 7;
            uint32_t so = SW(r * 128 + s * 16);
            size_t boff = (size_t)r * DIMD + k0 + s * 8;
            cpasync16(base + G1_B1OFF + so, w1p + boff);
            cpasync16(base + G1_B3OFF + so, w3p + boff);
        }
        cp_commit();
    };

    float accg[2][4][4] = {};
    float accu[2][4][4] = {};

    load_chunk(0, 0);
    load_chunk(1, 64);

    const int a_r = warp_m + (lid & 15);
    const int a_k8 = (lid >> 4) << 3;
    const int b_r = warp_n + (lid & 7) + ((lid & 16) ? 8 : 0);
    const int b_k8 = (lid & 8);

    for (int kk = 0; kk < G1_NK; kk++) {
        if (kk + 1 < G1_NK) cp_wait1(); else cp_wait0();
        __syncthreads();
        if (kk + 2 < G1_NK) load_chunk((kk + 2) % NSTAGE, (kk + 2) * 64);

        uint32_t base = sb + (kk % NSTAGE) * G1_STAGE;
#pragma unroll
        for (int k16 = 0; k16 < 64; k16 += 16) {
            uint32_t A[2][4];
            const int acol = (k16 + a_k8) * 2;
#pragma unroll
            for (int mi = 0; mi < 2; mi++)
                ldsm4(A[mi], base + SW((a_r + mi * 16) * 128 + acol));
            const int bcol = (k16 + b_k8) * 2;
            uint32_t Bg[2][4];
#pragma unroll
            for (int h = 0; h < 2; h++)
                ldsm4(Bg[h], base + G1_B1OFF + SW((b_r + h * 16) * 128 + bcol));
            uint32_t Bu[2][4];
#pragma unroll
            for (int h = 0; h < 2; h++)
                ldsm4(Bu[h], base + G1_B3OFF + SW((b_r + h * 16) * 128 + bcol));
#pragma unroll
            for (int mi = 0; mi < 2; mi++)
#pragma unroll
                for (int nt = 0; nt < 4; nt++)
                    mma16816(accg[mi][nt], A[mi], &Bg[nt >> 1][(nt & 1) * 2]);
#pragma unroll
            for (int mi = 0; mi < 2; mi++)
#pragma unroll
                for (int nt = 0; nt < 4; nt++)
                    mma16816(accu[mi][nt], A[mi], &Bu[nt >> 1][(nt & 1) * 2]);
        }
    }

    // Epilogue: SwiGLU (fast exp); store h as fp16
    const int g = lid >> 2, t = lid & 3;
#pragma unroll
    for (int mi = 0; mi < 2; mi++)
#pragma unroll
        for (int nt = 0; nt < 4; nt++) {
            int col = bn0 + warp_n + nt * 8 + t * 2;
#pragma unroll
            for (int half = 0; half < 2; half++) {
                int m = warp_m + mi * 16 + g + half * 8;
                if (m < rows) {
                    float gv0 = accg[mi][nt][half * 2 + 0];
                    float gv1 = accg[mi][nt][half * 2 + 1];
                    float uv0 = accu[mi][nt][half * 2 + 0];
                    float uv1 = accu[mi][nt][half * 2 + 1];
                    float h0 = gv0 / (1.f + __expf(-gv0)) * uv0;
                    float h1 = gv1 / (1.f + __expf(-gv1)) * uv1;
                    __half hh0 = __float2half_rn(h0);
                    __half hh1 = __float2half_rn(h1);
                    uint32_t Hp = (uint32_t)__half_as_ushort(hh0) | ((uint32_t)__half_as_ushort(hh1) << 16);
                    *(uint32_t*)(g_h + (size_t)(row0 + m) * HID + col) = Hp;
                }
            }
        }
}

// ---------------------------------------------------------------------------
// GEMM2: y = h * W2^T, fp16 out.
// CTA tile 128x128, warp tile 32x64 (4Mx2N warps). 2 CTAs/SM.
// Stage = [A 16KB | B 16KB]; 3-stage pipeline (96KB).
// ---------------------------------------------------------------------------
__global__ __launch_bounds__(256, 2) void gemm2_tc() {
    const int tileId = blockIdx.x;
    if (tileId >= g_ntiles) return;
    const int e    = g_tile_e[tileId];
    const int row0 = g_tile_row0[tileId];
    const int rows = g_tile_rows[tileId];
    const int bn0  = blockIdx.y * BN2;
    const int tid  = threadIdx.x;
    const int wid  = tid >> 5, lid = tid & 31;
    const int warp_m = (wid >> 1) * 32;   // 0,32,64,96
    const int warp_n = (wid & 1) * 64;    // 0,64

    extern __shared__ char dynsm[];
    uint32_t sb_raw = smem_u32(dynsm);
    uint32_t sb = (sb_raw + 1023u) & ~1023u;

    const __half* w2p = g_w2 + ((size_t)e * DIMD + bn0) * HID;

    auto load_chunk = [&](int st, int k0) {
        uint32_t base = sb + st * G2_STAGE;
#pragma unroll
        for (int i = 0; i < 4; i++) {               // A: 128x64
            int seg = tid + i * 256;
            int r = seg >> 3, s = seg & 7;
            int ar = r < rows ? r : rows - 1;
            uint32_t so = SW(r * 128 + s * 16);
            cpasync16(base + so, g_h + (size_t)(row0 + ar) * HID + k0 + s * 8);
        }
#pragma unroll
        for (int i = 0; i < 4; i++) {               // B: 128x64
            int seg = tid + i * 256;
            int r = seg >> 3, s = seg & 7;
            uint32_t so = SW(r * 128 + s * 16);
            cpasync16(base + G2_BOFF + so, w2p + (size_t)r * HID + k0 + s * 8);
        }
        cp_commit();
    };

    float acc[2][8][4] = {};

    load_chunk(0, 0);
    load_chunk(1, 64);

    const int a_r = warp_m + (lid & 15);
    const int a_k8 = (lid >> 4) << 3;
    const int b_r = warp_n + (lid & 7) + ((lid & 16) ? 8 : 0);
    const int b_k8 = (lid & 8);

    for (int kk = 0; kk < G2_NK; kk++) {
        if (kk + 1 < G2_NK) cp_wait1(); else cp_wait0();
        __syncthreads();
        if (kk + 2 < G2_NK) load_chunk((kk + 2) % NSTAGE, (kk + 2) * 64);

        uint32_t base = sb + (kk % NSTAGE) * G2_STAGE;
#pragma unroll
        for (int k16 = 0; k16 < 64; k16 += 16) {
            uint32_t A[2][4];
            const int acol = (k16 + a_k8) * 2;
#pragma unroll
            for (int mi = 0; mi < 2; mi++)
                ldsm4(A[mi], base + SW((a_r + mi * 16) * 128 + acol));
            const int bcol = (k16 + b_k8) * 2;
            uint32_t Bw[4][4];
#pragma unroll
            for (int h = 0; h < 4; h++)
                ldsm4(Bw[h], base + G2_BOFF + SW((b_r + h * 16) * 128 + bcol));
#pragma unroll
            for (int mi = 0; mi < 2; mi++)
#pragma unroll
                for (int nt = 0; nt < 8; nt++)
                    mma16816(acc[mi][nt], A[mi], &Bw[nt >> 1][(nt & 1) * 2]);
        }
    }

    // Epilogue: store y as fp16 (norm kernel re-scales in fp32)
    const int g = lid >> 2, t = lid & 3;
#pragma unroll
    for (int mi = 0; mi < 2; mi++)
#pragma unroll
        for (int nt = 0; nt < 8; nt++) {
            int col = bn0 + warp_n + nt * 8 + t * 2;
#pragma unroll
            for (int half = 0; half < 2; half++) {
                int m = warp_m + mi * 16 + g + half * 8;
                if (m < rows) {
                    __half v0 = __float2half_rn(acc[mi][nt][half * 2 + 0]);
                    __half v1 = __float2half_rn(acc[mi][nt][half * 2 + 1]);
                    uint32_t P = (uint32_t)__half_as_ushort(v0) | ((uint32_t)__half_as_ushort(v1) << 16);
                    *(uint32_t*)(g_y + (size_t)(row0 + m) * DIMD + col) = P;
                }
            }
        }
}

// ---------------------------------------------------------------------------
// RMSNorm + norm_w + scatter to token order. 2 rows per block, fp16 y input.
// ---------------------------------------------------------------------------
__global__ __launch_bounds__(256) void norm_kernel(
    const float* __restrict__ norm_w,
    const int* __restrict__ ids,
    float* __restrict__ out)
{
    const int half = threadIdx.x >> 7;
    const int ltid = threadIdx.x & 127;
    const int i    = blockIdx.x * 2 + half;
    const int tok  = g_perm[i];
    const int e    = ids[tok];
    const __half* yr = g_y + (size_t)i * DIMD;

    float s = 0.f;
    float yv[2][8];
#pragma unroll
    for (int it = 0; it < 2; it++) {
        int j = ltid * 8 + it * 128 * 8;
        uint4 pk = *(const uint4*)(yr + j);
        const uint32_t* pw = (const uint32_t*)&pk;
#pragma unroll
        for (int q = 0; q < 4; q++) {
            float2 f = __half22float2(*(const __half2*)&pw[q]);
            yv[it][q * 2 + 0] = f.x;
            yv[it][q * 2 + 1] = f.y;
            s += f.x * f.x + f.y * f.y;
        }
    }
#pragma unroll
    for (int o = 16; o; o >>= 1) s += __shfl_xor_sync(0xFFFFFFFFu, s, o);

    __shared__ float ws[2][4];
    __shared__ float stot[2];
    if ((ltid & 31) == 0) ws[half][ltid >> 5] = s;
    __syncthreads();
    if (ltid == 0)
        stot[half] = ws[half][0] + ws[half][1] + ws[half][2] + ws[half][3];
    __syncthreads();

    const float scale = rsqrtf(stot[half] * (1.0f / DIMD) + EPSV);
    const float* nw = norm_w + (size_t)e * DIMD;
    float* op = out + (size_t)tok * DIMD;
#pragma unroll
    for (int it = 0; it < 2; it++) {
        int j = ltid * 8 + it * 128 * 8;
#pragma unroll
        for (int q = 0; q < 2; q++) {
            float4 w = *(const float4*)(nw + j + q * 4);
            float4 r;
            r.x = yv[it][q * 4 + 0] * scale * w.x;
            r.y = yv[it][q * 4 + 1] * scale * w.y;
            r.z = yv[it][q * 4 + 2] * scale * w.z;
            r.w = yv[it][q * 4 + 3] * scale * w.w;
            *(float4*)(op + j + q * 4) = r;
        }
    }
}

// ---------------------------------------------------------------------------
extern "C" void kernel_launch(void* const* d_in, const int* in_sizes, int n_in,
                              void* d_out, int out_size) {
    const float* x      = (const float*)d_in[0];
    const float* w1     = (const float*)d_in[1];
    const float* w2     = (const float*)d_in[2];
    const float* w3     = (const float*)d_in[3];
    const float* norm_w = (const float*)d_in[4];
    const int*   ids    = (const int*)d_in[5];
    float* out = (float*)d_out;

    const int SMEM1 = NSTAGE * G1_STAGE + 1024;  // 99328 -> 2 CTAs/SM
    const int SMEM2 = NSTAGE * G2_STAGE + 1024;  // 99328 -> 2 CTAs/SM
    cudaFuncSetAttribute(gemm1_tc, cudaFuncAttributeMaxDynamicSharedMemorySize, SMEM1);
    cudaFuncSetAttribute(gemm2_tc, cudaFuncAttributeMaxDynamicSharedMemorySize, SMEM2);

    route_kernel<<<1, 256>>>(ids);
    cvt3_kernel<<<2960, 256>>>(w1, w3, x);

    // gemm1 grid: extra y-slice (y == HID/BN1) converts w2 in overlap.
    dim3 g1(MAX_TILES, HID / BN1 + 1);   // 68 x 61
    gemm1_tc<<<g1, 256, SMEM1>>>(w2);

    dim3 g2(MAX_TILES, DIMD / BN2);  // 68 x 16
    gemm2_tc<<<g2, 256, SMEM2>>>();

    norm_kernel<<<NTOK / 2, 256>>>(norm_w, ids, out);
}

// round 16
// speedup vs baseline: 1.0490x; 1.0490x over previous
#include <cuda_runtime.h>
#include <cuda_fp16.h>
#include <math.h>
#include <stdint.h>

// ---------------------------------------------------------------------------
// Problem constants
// ---------------------------------------------------------------------------
#define DIMD 2048
#define HID  3840
#define NTOK 8192
#define NEXP 4
#define EPSV 1e-5f
#define BM 128
#define BN1 64           // GEMM1 N-tile (gate+up dual output)
#define BN2 128          // GEMM2 N-tile
#define MAX_TILES (NTOK / BM + NEXP)

#define G1_NK (DIMD / 64)   // 32 K-chunks of 64
#define G2_NK (HID / 64)    // 60 K-chunks of 64
#define NSTAGE 3

// Stage layouts (bytes)
#define G1_STAGE 32768      // A 16KB + B1 8KB + B3 8KB
#define G1_B1OFF 16384
#define G1_B3OFF 24576
#define G2_STAGE 32768      // A 16KB + B 16KB
#define G2_BOFF  16384

// SW128 swizzle (Swizzle<3,4,3>) on byte offsets within a tile
#define SW(o) ((o) ^ (((o) >> 3) & 0x70))

// ---------------------------------------------------------------------------
// Scratch (device globals: allocation-free)
// ---------------------------------------------------------------------------
__device__ __half g_x[(size_t)NTOK * DIMD];
__device__ __half g_w1[(size_t)NEXP * HID * DIMD];
__device__ __half g_w3[(size_t)NEXP * HID * DIMD];
__device__ __half g_w2[(size_t)NEXP * DIMD * HID];
__device__ __half g_h[(size_t)NTOK * HID];
__device__ __half g_y[(size_t)NTOK * DIMD];
__device__ int   g_perm[NTOK];
__device__ int   g_tile_e[MAX_TILES];
__device__ int   g_tile_row0[MAX_TILES];
__device__ int   g_tile_rows[MAX_TILES];
__device__ int   g_ntiles;

// ---------------------------------------------------------------------------
// PTX helpers (sm_80-baseline)
// ---------------------------------------------------------------------------
__device__ __forceinline__ uint32_t smem_u32(const void* p) {
    uint32_t a;
    asm("{ .reg .u64 t; cvta.to.shared.u64 t, %1; cvt.u32.u64 %0, t; }" : "=r"(a) : "l"(p));
    return a;
}
__device__ __forceinline__ void cpasync16(uint32_t dst, const void* src) {
    asm volatile("cp.async.cg.shared.global [%0], [%1], 16;" :: "r"(dst), "l"(src) : "memory");
}
__device__ __forceinline__ void cp_commit() {
    asm volatile("cp.async.commit_group;" ::: "memory");
}
__device__ __forceinline__ void cp_wait1() {
    asm volatile("cp.async.wait_group 1;" ::: "memory");
}
__device__ __forceinline__ void cp_wait0() {
    asm volatile("cp.async.wait_group 0;" ::: "memory");
}
__device__ __forceinline__ void ldsm4(uint32_t* r, uint32_t addr) {
    asm volatile("ldmatrix.sync.aligned.m8n8.x4.shared.b16 {%0,%1,%2,%3}, [%4];"
                 : "=r"(r[0]), "=r"(r[1]), "=r"(r[2]), "=r"(r[3]) : "r"(addr));
}
__device__ __forceinline__ void mma16816(float* d, const uint32_t* a, const uint32_t* b) {
    asm volatile("mma.sync.aligned.m16n8k16.row.col.f32.f16.f16.f32 "
                 "{%0,%1,%2,%3}, {%4,%5,%6,%7}, {%8,%9}, {%0,%1,%2,%3};"
                 : "+f"(d[0]), "+f"(d[1]), "+f"(d[2]), "+f"(d[3])
                 : "r"(a[0]), "r"(a[1]), "r"(a[2]), "r"(a[3]), "r"(b[0]), "r"(b[1]));
}
__device__ __forceinline__ uint2 cvt4_f32_f16(float4 f) {
    __half h0 = __float2half_rn(f.x);
    __half h1 = __float2half_rn(f.y);
    __half h2 = __float2half_rn(f.z);
    __half h3 = __float2half_rn(f.w);
    uint2 H;
    H.x = (uint32_t)__half_as_ushort(h0) | ((uint32_t)__half_as_ushort(h1) << 16);
    H.y = (uint32_t)__half_as_ushort(h2) | ((uint32_t)__half_as_ushort(h3) << 16);
    return H;
}

// ---------------------------------------------------------------------------
// Routing
// ---------------------------------------------------------------------------
__global__ void route_kernel(const int* __restrict__ ids) {
    __shared__ int cnt[NEXP];
    __shared__ int cur[NEXP];
    int tid = threadIdx.x;
    if (tid < NEXP) cnt[tid] = 0;
    __syncthreads();
    for (int t = tid; t < NTOK; t += blockDim.x) atomicAdd(&cnt[ids[t]], 1);
    __syncthreads();
    if (tid == 0) {
        int o = 0, nt = 0;
        for (int e = 0; e < NEXP; e++) {
            cur[e] = o;
            int c = cnt[e];
            for (int r = 0; r < c; r += BM) {
                g_tile_e[nt] = e;
                g_tile_row0[nt] = o + r;
                g_tile_rows[nt] = (c - r) < BM ? (c - r) : BM;
                nt++;
            }
            o += c;
        }
        g_ntiles = nt;
    }
    __syncthreads();
    for (int t = tid; t < NTOK; t += blockDim.x) {
        int p = atomicAdd(&cur[ids[t]], 1);
        g_perm[p] = t;
    }
}

// ---------------------------------------------------------------------------
// fp32 -> fp16 (rn) for w1, w3, x. (w2 converts inside gemm1's y==0 slice.)
// ---------------------------------------------------------------------------
#define WN4 ((NEXP * HID * DIMD) / 4)
#define XN4 ((NTOK * DIMD) / 4)
#define TOT3N4 (2 * WN4 + XN4)

__global__ __launch_bounds__(256) void cvt3_kernel(
    const float* __restrict__ w1, const float* __restrict__ w3,
    const float* __restrict__ x)
{
    int stride = gridDim.x * blockDim.x;
    for (int i = blockIdx.x * blockDim.x + threadIdx.x; i < TOT3N4; i += stride) {
        const float4* src;
        uint2* dst;
        int j = i;
        if (j < WN4)               { src = (const float4*)w1; dst = (uint2*)g_w1; }
        else if ((j -= WN4) < WN4) { src = (const float4*)w3; dst = (uint2*)g_w3; }
        else { j -= WN4;             src = (const float4*)x;  dst = (uint2*)g_x; }
        dst[j] = cvt4_f32_f16(src[j]);
    }
}

// ---------------------------------------------------------------------------
// GEMM1: gate=X*W1^T, up=X*W3^T, h=silu(gate)*up.
// CTA tile 128x64, warp tile 32x32 (4Mx2N warps). 2 CTAs/SM.
// Stage = [A 16KB | B1 8KB | B3 8KB]; 3-stage cp.async pipeline (96KB).
// blockIdx.y == 0 is the w2-conversion slice (scheduled FIRST: x-fastest,
// y-last ordering means y=0 CTAs launch in wave 1 and overlap the GEMM).
// GEMM slices use bn0 = (blockIdx.y - 1) * BN1.
// ---------------------------------------------------------------------------
__global__ __launch_bounds__(256, 2) void gemm1_tc(const float* __restrict__ w2src) {
    const int tid  = threadIdx.x;

    if (blockIdx.y == 0) {
        // w2 conversion slice: grid-stride over WN4 float4s, overlapped
        // with the tensor-bound GEMM waves (DRAM is ~11% busy under them).
        const float4* src = (const float4*)w2src;
        uint2* dst = (uint2*)g_w2;
        int stride = MAX_TILES * 256;
        for (int i = blockIdx.x * 256 + tid; i < WN4; i += stride)
            dst[i] = cvt4_f32_f16(src[i]);
        return;
    }

    const int tileId = blockIdx.x;
    if (tileId >= g_ntiles) return;
    const int e    = g_tile_e[tileId];
    const int row0 = g_tile_row0[tileId];
    const int rows = g_tile_rows[tileId];
    const int bn0  = (blockIdx.y - 1) * BN1;
    const int wid  = tid >> 5, lid = tid & 31;
    const int warp_m = (wid >> 1) * 32;   // 0,32,64,96
    const int warp_n = (wid & 1) * 32;    // 0,32

    extern __shared__ char dynsm[];
    uint32_t sb_raw = smem_u32(dynsm);
    uint32_t sb = (sb_raw + 1023u) & ~1023u;

    __shared__ int rowTok[BM];
    if (tid < BM) rowTok[tid] = g_perm[row0 + (tid < rows ? tid : rows - 1)];
    __syncthreads();

    const __half* w1p = g_w1 + ((size_t)e * HID + bn0) * DIMD;
    const __half* w3p = g_w3 + ((size_t)e * HID + bn0) * DIMD;

    auto load_chunk = [&](int st, int k0) {
        uint32_t base = sb + st * G1_STAGE;
#pragma unroll
        for (int i = 0; i < 4; i++) {               // A: 128x64
            int seg = tid + i * 256;
            int r = seg >> 3, s = seg & 7;
            uint32_t so = SW(r * 128 + s * 16);
            cpasync16(base + so, g_x + (size_t)rowTok[r] * DIMD + k0 + s * 8);
        }
#pragma unroll
        for (int i = 0; i < 2; i++) {               // B1, B3: 64x64 each
            int seg = tid + i * 256;
            int r = seg >> 3, s = seg & 7;
            uint32_t so = SW(r * 128 + s * 16);
            size_t boff = (size_t)r * DIMD + k0 + s * 8;
            cpasync16(base + G1_B1OFF + so, w1p + boff);
            cpasync16(base + G1_B3OFF + so, w3p + boff);
        }
        cp_commit();
    };

    float accg[2][4][4] = {};
    float accu[2][4][4] = {};

    load_chunk(0, 0);
    load_chunk(1, 64);

    const int a_r = warp_m + (lid & 15);
    const int a_k8 = (lid >> 4) << 3;
    const int b_r = warp_n + (lid & 7) + ((lid & 16) ? 8 : 0);
    const int b_k8 = (lid & 8);

    for (int kk = 0; kk < G1_NK; kk++) {
        if (kk + 1 < G1_NK) cp_wait1(); else cp_wait0();
        __syncthreads();
        if (kk + 2 < G1_NK) load_chunk((kk + 2) % NSTAGE, (kk + 2) * 64);

        uint32_t base = sb + (kk % NSTAGE) * G1_STAGE;
#pragma unroll
        for (int k16 = 0; k16 < 64; k16 += 16) {
            uint32_t A[2][4];
            const int acol = (k16 + a_k8) * 2;
#pragma unroll
            for (int mi = 0; mi < 2; mi++)
                ldsm4(A[mi], base + SW((a_r + mi * 16) * 128 + acol));
            const int bcol = (k16 + b_k8) * 2;
            uint32_t Bg[2][4];
#pragma unroll
            for (int h = 0; h < 2; h++)
                ldsm4(Bg[h], base + G1_B1OFF + SW((b_r + h * 16) * 128 + bcol));
            uint32_t Bu[2][4];
#pragma unroll
            for (int h = 0; h < 2; h++)
                ldsm4(Bu[h], base + G1_B3OFF + SW((b_r + h * 16) * 128 + bcol));
#pragma unroll
            for (int mi = 0; mi < 2; mi++)
#pragma unroll
                for (int nt = 0; nt < 4; nt++)
                    mma16816(accg[mi][nt], A[mi], &Bg[nt >> 1][(nt & 1) * 2]);
#pragma unroll
            for (int mi = 0; mi < 2; mi++)
#pragma unroll
                for (int nt = 0; nt < 4; nt++)
                    mma16816(accu[mi][nt], A[mi], &Bu[nt >> 1][(nt & 1) * 2]);
        }
    }

    // Epilogue: SwiGLU (fast exp); store h as fp16
    const int g = lid >> 2, t = lid & 3;
#pragma unroll
    for (int mi = 0; mi < 2; mi++)
#pragma unroll
        for (int nt = 0; nt < 4; nt++) {
            int col = bn0 + warp_n + nt * 8 + t * 2;
#pragma unroll
            for (int half = 0; half < 2; half++) {
                int m = warp_m + mi * 16 + g + half * 8;
                if (m < rows) {
                    float gv0 = accg[mi][nt][half * 2 + 0];
                    float gv1 = accg[mi][nt][half * 2 + 1];
                    float uv0 = accu[mi][nt][half * 2 + 0];
                    float uv1 = accu[mi][nt][half * 2 + 1];
                    float h0 = gv0 / (1.f + __expf(-gv0)) * uv0;
                    float h1 = gv1 / (1.f + __expf(-gv1)) * uv1;
                    __half hh0 = __float2half_rn(h0);
                    __half hh1 = __float2half_rn(h1);
                    uint32_t Hp = (uint32_t)__half_as_ushort(hh0) | ((uint32_t)__half_as_ushort(hh1) << 16);
                    *(uint32_t*)(g_h + (size_t)(row0 + m) * HID + col) = Hp;
                }
            }
        }
}

// ---------------------------------------------------------------------------
// GEMM2: y = h * W2^T, fp16 out.
// CTA tile 128x128, warp tile 32x64 (4Mx2N warps). 2 CTAs/SM.
// Stage = [A 16KB | B 16KB]; 3-stage pipeline (96KB).
// ---------------------------------------------------------------------------
__global__ __launch_bounds__(256, 2) void gemm2_tc() {
    const int tileId = blockIdx.x;
    if (tileId >= g_ntiles) return;
    const int e    = g_tile_e[tileId];
    const int row0 = g_tile_row0[tileId];
    const int rows = g_tile_rows[tileId];
    const int bn0  = blockIdx.y * BN2;
    const int tid  = threadIdx.x;
    const int wid  = tid >> 5, lid = tid & 31;
    const int warp_m = (wid >> 1) * 32;   // 0,32,64,96
    const int warp_n = (wid & 1) * 64;    // 0,64

    extern __shared__ char dynsm[];
    uint32_t sb_raw = smem_u32(dynsm);
    uint32_t sb = (sb_raw + 1023u) & ~1023u;

    const __half* w2p = g_w2 + ((size_t)e * DIMD + bn0) * HID;

    auto load_chunk = [&](int st, int k0) {
        uint32_t base = sb + st * G2_STAGE;
#pragma unroll
        for (int i = 0; i < 4; i++) {               // A: 128x64
            int seg = tid + i * 256;
            int r = seg >> 3, s = seg & 7;
            int ar = r < rows ? r : rows - 1;
            uint32_t so = SW(r * 128 + s * 16);
            cpasync16(base + so, g_h + (size_t)(row0 + ar) * HID + k0 + s * 8);
        }
#pragma unroll
        for (int i = 0; i < 4; i++) {               // B: 128x64
            int seg = tid + i * 256;
            int r = seg >> 3, s = seg & 7;
            uint32_t so = SW(r * 128 + s * 16);
            cpasync16(base + G2_BOFF + so, w2p + (size_t)r * HID + k0 + s * 8);
        }
        cp_commit();
    };

    float acc[2][8][4] = {};

    load_chunk(0, 0);
    load_chunk(1, 64);

    const int a_r = warp_m + (lid & 15);
    const int a_k8 = (lid >> 4) << 3;
    const int b_r = warp_n + (lid & 7) + ((lid & 16) ? 8 : 0);
    const int b_k8 = (lid & 8);

    for (int kk = 0; kk < G2_NK; kk++) {
        if (kk + 1 < G2_NK) cp_wait1(); else cp_wait0();
        __syncthreads();
        if (kk + 2 < G2_NK) load_chunk((kk + 2) % NSTAGE, (kk + 2) * 64);

        uint32_t base = sb + (kk % NSTAGE) * G2_STAGE;
#pragma unroll
        for (int k16 = 0; k16 < 64; k16 += 16) {
            uint32_t A[2][4];
            const int acol = (k16 + a_k8) * 2;
#pragma unroll
            for (int mi = 0; mi < 2; mi++)
                ldsm4(A[mi], base + SW((a_r + mi * 16) * 128 + acol));
            const int bcol = (k16 + b_k8) * 2;
            uint32_t Bw[4][4];
#pragma unroll
            for (int h = 0; h < 4; h++)
                ldsm4(Bw[h], base + G2_BOFF + SW((b_r + h * 16) * 128 + bcol));
#pragma unroll
            for (int mi = 0; mi < 2; mi++)
#pragma unroll
                for (int nt = 0; nt < 8; nt++)
                    mma16816(acc[mi][nt], A[mi], &Bw[nt >> 1][(nt & 1) * 2]);
        }
    }

    // Epilogue: store y as fp16 (norm kernel re-scales in fp32)
    const int g = lid >> 2, t = lid & 3;
#pragma unroll
    for (int mi = 0; mi < 2; mi++)
#pragma unroll
        for (int nt = 0; nt < 8; nt++) {
            int col = bn0 + warp_n + nt * 8 + t * 2;
#pragma unroll
            for (int half = 0; half < 2; half++) {
                int m = warp_m + mi * 16 + g + half * 8;
                if (m < rows) {
                    __half v0 = __float2half_rn(acc[mi][nt][half * 2 + 0]);
                    __half v1 = __float2half_rn(acc[mi][nt][half * 2 + 1]);
                    uint32_t P = (uint32_t)__half_as_ushort(v0) | ((uint32_t)__half_as_ushort(v1) << 16);
                    *(uint32_t*)(g_y + (size_t)(row0 + m) * DIMD + col) = P;
                }
            }
        }
}

// ---------------------------------------------------------------------------
// RMSNorm + norm_w + scatter to token order. 2 rows per block, fp16 y input.
// ---------------------------------------------------------------------------
__global__ __launch_bounds__(256) void norm_kernel(
    const float* __restrict__ norm_w,
    const int* __restrict__ ids,
    float* __restrict__ out)
{
    const int half = threadIdx.x >> 7;
    const int ltid = threadIdx.x & 127;
    const int i    = blockIdx.x * 2 + half;
    const int tok  = g_perm[i];
    const int e    = ids[tok];
    const __half* yr = g_y + (size_t)i * DIMD;

    float s = 0.f;
    float yv[2][8];
#pragma unroll
    for (int it = 0; it < 2; it++) {
        int j = ltid * 8 + it * 128 * 8;
        uint4 pk = *(const uint4*)(yr + j);
        const uint32_t* pw = (const uint32_t*)&pk;
#pragma unroll
        for (int q = 0; q < 4; q++) {
            float2 f = __half22float2(*(const __half2*)&pw[q]);
            yv[it][q * 2 + 0] = f.x;
            yv[it][q * 2 + 1] = f.y;
            s += f.x * f.x + f.y * f.y;
        }
    }
#pragma unroll
    for (int o = 16; o; o >>= 1) s += __shfl_xor_sync(0xFFFFFFFFu, s, o);

    __shared__ float ws[2][4];
    __shared__ float stot[2];
    if ((ltid & 31) == 0) ws[half][ltid >> 5] = s;
    __syncthreads();
    if (ltid == 0)
        stot[half] = ws[half][0] + ws[half][1] + ws[half][2] + ws[half][3];
    __syncthreads();

    const float scale = rsqrtf(stot[half] * (1.0f / DIMD) + EPSV);
    const float* nw = norm_w + (size_t)e * DIMD;
    float* op = out + (size_t)tok * DIMD;
#pragma unroll
    for (int it = 0; it < 2; it++) {
        int j = ltid * 8 + it * 128 * 8;
#pragma unroll
        for (int q = 0; q < 2; q++) {
            float4 w = *(const float4*)(nw + j + q * 4);
            float4 r;
            r.x = yv[it][q * 4 + 0] * scale * w.x;
            r.y = yv[it][q * 4 + 1] * scale * w.y;
            r.z = yv[it][q * 4 + 2] * scale * w.z;
            r.w = yv[it][q * 4 + 3] * scale * w.w;
            *(float4*)(op + j + q * 4) = r;
        }
    }
}

// ---------------------------------------------------------------------------
extern "C" void kernel_launch(void* const* d_in, const int* in_sizes, int n_in,
                              void* d_out, int out_size) {
    const float* x      = (const float*)d_in[0];
    const float* w1     = (const float*)d_in[1];
    const float* w2     = (const float*)d_in[2];
    const float* w3     = (const float*)d_in[3];
    const float* norm_w = (const float*)d_in[4];
    const int*   ids    = (const int*)d_in[5];
    float* out = (float*)d_out;

    const int SMEM1 = NSTAGE * G1_STAGE + 1024;  // 99328 -> 2 CTAs/SM
    const int SMEM2 = NSTAGE * G2_STAGE + 1024;  // 99328 -> 2 CTAs/SM
    cudaFuncSetAttribute(gemm1_tc, cudaFuncAttributeMaxDynamicSharedMemorySize, SMEM1);
    cudaFuncSetAttribute(gemm2_tc, cudaFuncAttributeMaxDynamicSharedMemorySize, SMEM2);

    route_kernel<<<1, 256>>>(ids);
    cvt3_kernel<<<2960, 256>>>(w1, w3, x);

    // gemm1 grid: y==0 slice converts w2 in overlap (scheduled first),
    // y in [1, HID/BN1] are the GEMM slices.
    dim3 g1(MAX_TILES, HID / BN1 + 1);   // 68 x 61
    gemm1_tc<<<g1, 256, SMEM1>>>(w2);

    dim3 g2(MAX_TILES, DIMD / BN2);  // 68 x 16
    gemm2_tc<<<g2, 256, SMEM2>>>();

    norm_kernel<<<NTOK / 2, 256>>>(norm_w, ids, out);
}

// round 17
// speedup vs baseline: 1.0617x; 1.0121x over previous
#include <cuda_runtime.h>
#include <cuda_fp16.h>
#include <math.h>
#include <stdint.h>

// ---------------------------------------------------------------------------
// Problem constants
// ---------------------------------------------------------------------------
#define DIMD 2048
#define HID  3840
#define NTOK 8192
#define NEXP 4
#define EPSV 1e-5f
#define BM 128
#define BN1 64           // GEMM1 N-tile (gate+up dual output)
#define BN2 128          // GEMM2 N-tile
#define MAX_TILES (NTOK / BM + NEXP)

#define G1_NK (DIMD / 64)   // 32 K-chunks of 64
#define G2_NK (HID / 64)    // 60 K-chunks of 64
#define NSTAGE 3

// Stage layouts (bytes)
#define G1_STAGE 32768      // A 16KB + B1 8KB + B3 8KB
#define G1_B1OFF 16384
#define G1_B3OFF 24576
#define G2_STAGE 32768      // A 16KB + B 16KB
#define G2_BOFF  16384

// SW128 swizzle (Swizzle<3,4,3>) on byte offsets within a tile
#define SW(o) ((o) ^ (((o) >> 3) & 0x70))

// ---------------------------------------------------------------------------
// Scratch (device globals: allocation-free)
// ---------------------------------------------------------------------------
__device__ __half g_x[(size_t)NTOK * DIMD];
__device__ __half g_w1[(size_t)NEXP * HID * DIMD];
__device__ __half g_w3[(size_t)NEXP * HID * DIMD];
__device__ __half g_w2[(size_t)NEXP * DIMD * HID];
__device__ __half g_h[(size_t)NTOK * HID];
__device__ __half g_y[(size_t)NTOK * DIMD];
__device__ int   g_perm[NTOK];
__device__ int   g_tile_e[MAX_TILES];
__device__ int   g_tile_row0[MAX_TILES];
__device__ int   g_tile_rows[MAX_TILES];
__device__ int   g_ntiles;

// ---------------------------------------------------------------------------
// PTX helpers (sm_80-baseline)
// ---------------------------------------------------------------------------
__device__ __forceinline__ uint32_t smem_u32(const void* p) {
    uint32_t a;
    asm("{ .reg .u64 t; cvta.to.shared.u64 t, %1; cvt.u32.u64 %0, t; }" : "=r"(a) : "l"(p));
    return a;
}
__device__ __forceinline__ void cpasync16(uint32_t dst, const void* src) {
    asm volatile("cp.async.cg.shared.global [%0], [%1], 16;" :: "r"(dst), "l"(src) : "memory");
}
__device__ __forceinline__ void cp_commit() {
    asm volatile("cp.async.commit_group;" ::: "memory");
}
__device__ __forceinline__ void cp_wait1() {
    asm volatile("cp.async.wait_group 1;" ::: "memory");
}
__device__ __forceinline__ void cp_wait0() {
    asm volatile("cp.async.wait_group 0;" ::: "memory");
}
__device__ __forceinline__ void ldsm4(uint32_t* r, uint32_t addr) {
    asm volatile("ldmatrix.sync.aligned.m8n8.x4.shared.b16 {%0,%1,%2,%3}, [%4];"
                 : "=r"(r[0]), "=r"(r[1]), "=r"(r[2]), "=r"(r[3]) : "r"(addr));
}
__device__ __forceinline__ void mma16816(float* d, const uint32_t* a, const uint32_t* b) {
    asm volatile("mma.sync.aligned.m16n8k16.row.col.f32.f16.f16.f32 "
                 "{%0,%1,%2,%3}, {%4,%5,%6,%7}, {%8,%9}, {%0,%1,%2,%3};"
                 : "+f"(d[0]), "+f"(d[1]), "+f"(d[2]), "+f"(d[3])
                 : "r"(a[0]), "r"(a[1]), "r"(a[2]), "r"(a[3]), "r"(b[0]), "r"(b[1]));
}
__device__ __forceinline__ uint2 cvt4_f32_f16(float4 f) {
    __half h0 = __float2half_rn(f.x);
    __half h1 = __float2half_rn(f.y);
    __half h2 = __float2half_rn(f.z);
    __half h3 = __float2half_rn(f.w);
    uint2 H;
    H.x = (uint32_t)__half_as_ushort(h0) | ((uint32_t)__half_as_ushort(h1) << 16);
    H.y = (uint32_t)__half_as_ushort(h2) | ((uint32_t)__half_as_ushort(h3) << 16);
    return H;
}

// ---------------------------------------------------------------------------
// Fused: fp32 -> fp16 (rn) for w1, w3, x; the LAST block does the routing.
// (Routing is independent of the conversion data; it rides under the
// memory-bound conversion blocks. w2 converts inside gemm1's y==0 slice.)
// ---------------------------------------------------------------------------
#define WN4 ((NEXP * HID * DIMD) / 4)
#define XN4 ((NTOK * DIMD) / 4)
#define TOT3N4 (2 * WN4 + XN4)
#define CVT_BLOCKS 2960

__global__ __launch_bounds__(256) void cvt3_route_kernel(
    const float* __restrict__ w1, const float* __restrict__ w3,
    const float* __restrict__ x, const int* __restrict__ ids)
{
    const int tid = threadIdx.x;

    if (blockIdx.x == CVT_BLOCKS) {
        // Routing block (single CTA, self-contained).
        __shared__ int cnt[NEXP];
        __shared__ int cur[NEXP];
        if (tid < NEXP) cnt[tid] = 0;
        __syncthreads();
        for (int t = tid; t < NTOK; t += blockDim.x) atomicAdd(&cnt[ids[t]], 1);
        __syncthreads();
        if (tid == 0) {
            int o = 0, nt = 0;
            for (int e = 0; e < NEXP; e++) {
                cur[e] = o;
                int c = cnt[e];
                for (int r = 0; r < c; r += BM) {
                    g_tile_e[nt] = e;
                    g_tile_row0[nt] = o + r;
                    g_tile_rows[nt] = (c - r) < BM ? (c - r) : BM;
                    nt++;
                }
                o += c;
            }
            g_ntiles = nt;
        }
        __syncthreads();
        for (int t = tid; t < NTOK; t += blockDim.x) {
            int p = atomicAdd(&cur[ids[t]], 1);
            g_perm[p] = t;
        }
        return;
    }

    int stride = CVT_BLOCKS * 256;
    for (int i = blockIdx.x * 256 + tid; i < TOT3N4; i += stride) {
        const float4* src;
        uint2* dst;
        int j = i;
        if (j < WN4)               { src = (const float4*)w1; dst = (uint2*)g_w1; }
        else if ((j -= WN4) < WN4) { src = (const float4*)w3; dst = (uint2*)g_w3; }
        else { j -= WN4;             src = (const float4*)x;  dst = (uint2*)g_x; }
        dst[j] = cvt4_f32_f16(src[j]);
    }
}

// ---------------------------------------------------------------------------
// GEMM1: gate=X*W1^T, up=X*W3^T, h=silu(gate)*up.
// CTA tile 128x64, warp tile 32x32 (4Mx2N warps). 2 CTAs/SM.
// Stage = [A 16KB | B1 8KB | B3 8KB]; 3-stage cp.async pipeline (96KB).
// blockIdx.y == 0 is the w2-conversion slice (scheduled FIRST: x-fastest,
// y-last ordering means y=0 CTAs launch in wave 1 and overlap the GEMM).
// GEMM slices use bn0 = (blockIdx.y - 1) * BN1.
// ---------------------------------------------------------------------------
__global__ __launch_bounds__(256, 2) void gemm1_tc(const float* __restrict__ w2src) {
    const int tid  = threadIdx.x;

    if (blockIdx.y == 0) {
        // w2 conversion slice: grid-stride over WN4 float4s, overlapped
        // with the tensor-bound GEMM waves (DRAM is ~11% busy under them).
        const float4* src = (const float4*)w2src;
        uint2* dst = (uint2*)g_w2;
        int stride = MAX_TILES * 256;
        for (int i = blockIdx.x * 256 + tid; i < WN4; i += stride)
            dst[i] = cvt4_f32_f16(src[i]);
        return;
    }

    const int tileId = blockIdx.x;
    if (tileId >= g_ntiles) return;
    const int e    = g_tile_e[tileId];
    const int row0 = g_tile_row0[tileId];
    const int rows = g_tile_rows[tileId];
    const int bn0  = (blockIdx.y - 1) * BN1;
    const int wid  = tid >> 5, lid = tid & 31;
    const int warp_m = (wid >> 1) * 32;   // 0,32,64,96
    const int warp_n = (wid & 1) * 32;    // 0,32

    extern __shared__ char dynsm[];
    uint32_t sb_raw = smem_u32(dynsm);
    uint32_t sb = (sb_raw + 1023u) & ~1023u;

    __shared__ int rowTok[BM];
    if (tid < BM) rowTok[tid] = g_perm[row0 + (tid < rows ? tid : rows - 1)];
    __syncthreads();

    const __half* w1p = g_w1 + ((size_t)e * HID + bn0) * DIMD;
    const __half* w3p = g_w3 + ((size_t)e * HID + bn0) * DIMD;

    auto load_chunk = [&](int st, int k0) {
        uint32_t base = sb + st * G1_STAGE;
#pragma unroll
        for (int i = 0; i < 4; i++) {               // A: 128x64
            int seg = tid + i * 256;
            int r = seg >> 3, s = seg & 7;
            uint32_t so = SW(r * 128 + s * 16);
            cpasync16(base + so, g_x + (size_t)rowTok[r] * DIMD + k0 + s * 8);
        }
#pragma unroll
        for (int i = 0; i < 2; i++) {               // B1, B3: 64x64 each
            int seg = tid + i * 256;
            int r = seg >> 3, s = seg & 7;
            uint32_t so = SW(r * 128 + s * 16);
            size_t boff = (size_t)r * DIMD + k0 + s * 8;
            cpasync16(base + G1_B1OFF + so, w1p + boff);
            cpasync16(base + G1_B3OFF + so, w3p + boff);
        }
        cp_commit();
    };

    float accg[2][4][4] = {};
    float accu[2][4][4] = {};

    load_chunk(0, 0);
    load_chunk(1, 64);

    const int a_r = warp_m + (lid & 15);
    const int a_k8 = (lid >> 4) << 3;
    const int b_r = warp_n + (lid & 7) + ((lid & 16) ? 8 : 0);
    const int b_k8 = (lid & 8);

    for (int kk = 0; kk < G1_NK; kk++) {
        if (kk + 1 < G1_NK) cp_wait1(); else cp_wait0();
        __syncthreads();
        if (kk + 2 < G1_NK) load_chunk((kk + 2) % NSTAGE, (kk + 2) * 64);

        uint32_t base = sb + (kk % NSTAGE) * G1_STAGE;
#pragma unroll
        for (int k16 = 0; k16 < 64; k16 += 16) {
            uint32_t A[2][4];
            const int acol = (k16 + a_k8) * 2;
#pragma unroll
            for (int mi = 0; mi < 2; mi++)
                ldsm4(A[mi], base + SW((a_r + mi * 16) * 128 + acol));
            const int bcol = (k16 + b_k8) * 2;
            uint32_t Bg[2][4];
#pragma unroll
            for (int h = 0; h < 2; h++)
                ldsm4(Bg[h], base + G1_B1OFF + SW((b_r + h * 16) * 128 + bcol));
            uint32_t Bu[2][4];
#pragma unroll
            for (int h = 0; h < 2; h++)
                ldsm4(Bu[h], base + G1_B3OFF + SW((b_r + h * 16) * 128 + bcol));
#pragma unroll
            for (int mi = 0; mi < 2; mi++)
#pragma unroll
                for (int nt = 0; nt < 4; nt++)
                    mma16816(accg[mi][nt], A[mi], &Bg[nt >> 1][(nt & 1) * 2]);
#pragma unroll
            for (int mi = 0; mi < 2; mi++)
#pragma unroll
                for (int nt = 0; nt < 4; nt++)
                    mma16816(accu[mi][nt], A[mi], &Bu[nt >> 1][(nt & 1) * 2]);
        }
    }

    // Epilogue: SwiGLU (fast exp); store h as fp16
    const int g = lid >> 2, t = lid & 3;
#pragma unroll
    for (int mi = 0; mi < 2; mi++)
#pragma unroll
        for (int nt = 0; nt < 4; nt++) {
            int col = bn0 + warp_n + nt * 8 + t * 2;
#pragma unroll
            for (int half = 0; half < 2; half++) {
                int m = warp_m + mi * 16 + g + half * 8;
                if (m < rows) {
                    float gv0 = accg[mi][nt][half * 2 + 0];
                    float gv1 = accg[mi][nt][half * 2 + 1];
                    float uv0 = accu[mi][nt][half * 2 + 0];
                    float uv1 = accu[mi][nt][half * 2 + 1];
                    float h0 = gv0 / (1.f + __expf(-gv0)) * uv0;
                    float h1 = gv1 / (1.f + __expf(-gv1)) * uv1;
                    __half hh0 = __float2half_rn(h0);
                    __half hh1 = __float2half_rn(h1);
                    uint32_t Hp = (uint32_t)__half_as_ushort(hh0) | ((uint32_t)__half_as_ushort(hh1) << 16);
                    *(uint32_t*)(g_h + (size_t)(row0 + m) * HID + col) = Hp;
                }
            }
        }
}

// ---------------------------------------------------------------------------
// GEMM2: y = h * W2^T, fp16 out.
// CTA tile 128x128, warp tile 32x64 (4Mx2N warps). 2 CTAs/SM.
// Stage = [A 16KB | B 16KB]; 3-stage pipeline (96KB).
// ---------------------------------------------------------------------------
__global__ __launch_bounds__(256, 2) void gemm2_tc() {
    const int tileId = blockIdx.x;
    if (tileId >= g_ntiles) return;
    const int e    = g_tile_e[tileId];
    const int row0 = g_tile_row0[tileId];
    const int rows = g_tile_rows[tileId];
    const int bn0  = blockIdx.y * BN2;
    const int tid  = threadIdx.x;
    const int wid  = tid >> 5, lid = tid & 31;
    const int warp_m = (wid >> 1) * 32;   // 0,32,64,96
    const int warp_n = (wid & 1) * 64;    // 0,64

    extern __shared__ char dynsm[];
    uint32_t sb_raw = smem_u32(dynsm);
    uint32_t sb = (sb_raw + 1023u) & ~1023u;

    const __half* w2p = g_w2 + ((size_t)e * DIMD + bn0) * HID;

    auto load_chunk = [&](int st, int k0) {
        uint32_t base = sb + st * G2_STAGE;
#pragma unroll
        for (int i = 0; i < 4; i++) {               // A: 128x64
            int seg = tid + i * 256;
            int r = seg >> 3, s = seg & 7;
            int ar = r < rows ? r : rows - 1;
            uint32_t so = SW(r * 128 + s * 16);
            cpasync16(base + so, g_h + (size_t)(row0 + ar) * HID + k0 + s * 8);
        }
#pragma unroll
        for (int i = 0; i < 4; i++) {               // B: 128x64
            int seg = tid + i * 256;
            int r = seg >> 3, s = seg & 7;
            uint32_t so = SW(r * 128 + s * 16);
            cpasync16(base + G2_BOFF + so, w2p + (size_t)r * HID + k0 + s * 8);
        }
        cp_commit();
    };

    float acc[2][8][4] = {};

    load_chunk(0, 0);
    load_chunk(1, 64);

    const int a_r = warp_m + (lid & 15);
    const int a_k8 = (lid >> 4) << 3;
    const int b_r = warp_n + (lid & 7) + ((lid & 16) ? 8 : 0);
    const int b_k8 = (lid & 8);

    for (int kk = 0; kk < G2_NK; kk++) {
        if (kk + 1 < G2_NK) cp_wait1(); else cp_wait0();
        __syncthreads();
        if (kk + 2 < G2_NK) load_chunk((kk + 2) % NSTAGE, (kk + 2) * 64);

        uint32_t base = sb + (kk % NSTAGE) * G2_STAGE;
#pragma unroll
        for (int k16 = 0; k16 < 64; k16 += 16) {
            uint32_t A[2][4];
            const int acol = (k16 + a_k8) * 2;
#pragma unroll
            for (int mi = 0; mi < 2; mi++)
                ldsm4(A[mi], base + SW((a_r + mi * 16) * 128 + acol));
            const int bcol = (k16 + b_k8) * 2;
            uint32_t Bw[4][4];
#pragma unroll
            for (int h = 0; h < 4; h++)
                ldsm4(Bw[h], base + G2_BOFF + SW((b_r + h * 16) * 128 + bcol));
#pragma unroll
            for (int mi = 0; mi < 2; mi++)
#pragma unroll
                for (int nt = 0; nt < 8; nt++)
                    mma16816(acc[mi][nt], A[mi], &Bw[nt >> 1][(nt & 1) * 2]);
        }
    }

    // Epilogue: store y as fp16 (norm kernel re-scales in fp32)
    const int g = lid >> 2, t = lid & 3;
#pragma unroll
    for (int mi = 0; mi < 2; mi++)
#pragma unroll
        for (int nt = 0; nt < 8; nt++) {
            int col = bn0 + warp_n + nt * 8 + t * 2;
#pragma unroll
            for (int half = 0; half < 2; half++) {
                int m = warp_m + mi * 16 + g + half * 8;
                if (m < rows) {
                    __half v0 = __float2half_rn(acc[mi][nt][half * 2 + 0]);
                    __half v1 = __float2half_rn(acc[mi][nt][half * 2 + 1]);
                    uint32_t P = (uint32_t)__half_as_ushort(v0) | ((uint32_t)__half_as_ushort(v1) << 16);
                    *(uint32_t*)(g_y + (size_t)(row0 + m) * DIMD + col) = P;
                }
            }
        }
}

// ---------------------------------------------------------------------------
// RMSNorm + norm_w + scatter to token order. 2 rows per block, fp16 y input.
// ---------------------------------------------------------------------------
__global__ __launch_bounds__(256) void norm_kernel(
    const float* __restrict__ norm_w,
    const int* __restrict__ ids,
    float* __restrict__ out)
{
    const int half = threadIdx.x >> 7;
    const int ltid = threadIdx.x & 127;
    const int i    = blockIdx.x * 2 + half;
    const int tok  = g_perm[i];
    const int e    = ids[tok];
    const __half* yr = g_y + (size_t)i * DIMD;

    float s = 0.f;
    float yv[2][8];
#pragma unroll
    for (int it = 0; it < 2; it++) {
        int j = ltid * 8 + it * 128 * 8;
        uint4 pk = *(const uint4*)(yr + j);
        const uint32_t* pw = (const uint32_t*)&pk;
#pragma unroll
        for (int q = 0; q < 4; q++) {
            float2 f = __half22float2(*(const __half2*)&pw[q]);
            yv[it][q * 2 + 0] = f.x;
            yv[it][q * 2 + 1] = f.y;
            s += f.x * f.x + f.y * f.y;
        }
    }
#pragma unroll
    for (int o = 16; o; o >>= 1) s += __shfl_xor_sync(0xFFFFFFFFu, s, o);

    __shared__ float ws[2][4];
    __shared__ float stot[2];
    if ((ltid & 31) == 0) ws[half][ltid >> 5] = s;
    __syncthreads();
    if (ltid == 0)
        stot[half] = ws[half][0] + ws[half][1] + ws[half][2] + ws[half][3];
    __syncthreads();

    const float scale = rsqrtf(stot[half] * (1.0f / DIMD) + EPSV);
    const float* nw = norm_w + (size_t)e * DIMD;
    float* op = out + (size_t)tok * DIMD;
#pragma unroll
    for (int it = 0; it < 2; it++) {
        int j = ltid * 8 + it * 128 * 8;
#pragma unroll
        for (int q = 0; q < 2; q++) {
            float4 w = *(const float4*)(nw + j + q * 4);
            float4 r;
            r.x = yv[it][q * 4 + 0] * scale * w.x;
            r.y = yv[it][q * 4 + 1] * scale * w.y;
            r.z = yv[it][q * 4 + 2] * scale * w.z;
            r.w = yv[it][q * 4 + 3] * scale * w.w;
            *(float4*)(op + j + q * 4) = r;
        }
    }
}

// ---------------------------------------------------------------------------
extern "C" void kernel_launch(void* const* d_in, const int* in_sizes, int n_in,
                              void* d_out, int out_size) {
    const float* x      = (const float*)d_in[0];
    const float* w1     = (const float*)d_in[1];
    const float* w2     = (const float*)d_in[2];
    const float* w3     = (const float*)d_in[3];
    const float* norm_w = (const float*)d_in[4];
    const int*   ids    = (const int*)d_in[5];
    float* out = (float*)d_out;

    const int SMEM1 = NSTAGE * G1_STAGE + 1024;  // 99328 -> 2 CTAs/SM
    const int SMEM2 = NSTAGE * G2_STAGE + 1024;  // 99328 -> 2 CTAs/SM
    cudaFuncSetAttribute(gemm1_tc, cudaFuncAttributeMaxDynamicSharedMemorySize, SMEM1);
    cudaFuncSetAttribute(gemm2_tc, cudaFuncAttributeMaxDynamicSharedMemorySize, SMEM2);

    // Fused conversion (w1, w3, x) + routing (last block).
    cvt3_route_kernel<<<CVT_BLOCKS + 1, 256>>>(w1, w3, x, ids);

    // gemm1 grid: y==0 slice converts w2 in overlap (scheduled first),
    // y in [1, HID/BN1] are the GEMM slices.
    dim3 g1(MAX_TILES, HID / BN1 + 1);   // 68 x 61
    gemm1_tc<<<g1, 256, SMEM1>>>(w2);

    dim3 g2(MAX_TILES, DIMD / BN2);  // 68 x 16
    gemm2_tc<<<g2, 256, SMEM2>>>();

    norm_kernel<<<NTOK / 2, 256>>>(norm_w, ids, out);
}